// round 3
// baseline (speedup 1.0000x reference)
#include <cuda_runtime.h>
#include <cstdint>

#define Nn 2048
#define Dd 128
#define Cc 512
#define Kp 1024
#define TINV 14.285714285714286f

// ----------------- scratch (device globals; allocation-free) -----------------
__device__ float    g_fes[Nn*Dd], g_fet[Nn*Dd];
__device__ unsigned g_Abits[Nn*64];
__device__ int      g_deg[Nn];
__device__ float    g_dinv[Nn];
__device__ float    g_h1t[Nn*Dd], g_h1s[Nn*Dd], g_h2t[Nn*Dd], g_h2s[Nn*Dd];
__device__ float    g_fgt[Nn*Dd], g_fgs[Nn*Dd];
__device__ float    g_rowp1[32*Nn], g_colp1[32*Nn];
__device__ float    g_pos1[Nn];
__device__ float    g_scores[Nn];
__device__ int      g_rank[Nn];
__device__ int      g_selidx[Kp];
__device__ float    g_selval[Kp];
__device__ float    g_nht[Kp*Dd], g_nhs[Kp*Dd];
__device__ unsigned g_Pbits[Kp*32];
__device__ float    g_dinvp[Kp];
__device__ float    g_ph1t[Kp*Dd], g_ph1s[Kp*Dd];
__device__ float    g_fpt[Kp*Dd], g_fps[Kp*Dd];
__device__ float    g_rowp2[16*Kp], g_colp2[16*Kp];
__device__ float    g_pos2[Kp];
__device__ float    g_terms1[Nn], g_terms2[Kp];

// ----------------- kernels -----------------

__global__ void zero_deg_kernel() {
    int i = blockIdx.x * blockDim.x + threadIdx.x;
    if (i < Nn) g_deg[i] = 0;
}

// OUT[16 rows] = X @ W_embed + b  (raw, l2norm applied separately)
// grid (Nn/16, 2): y=0 -> fs->g_fes, y=1 -> ft->g_fet. 128 threads (d).
__global__ void embed_kernel(const float* __restrict__ fs, const float* __restrict__ ft,
                             const float* __restrict__ W, const float* __restrict__ b) {
    const float* X = blockIdx.y ? ft : fs;
    float* OUT = blockIdx.y ? g_fet : g_fes;
    int d = threadIdx.x;
    int R0 = blockIdx.x * 16;
    __shared__ float srow[16][64];
    __shared__ float sW[64][Dd];
    float acc[16];
#pragma unroll
    for (int r = 0; r < 16; r++) acc[r] = 0.f;
    for (int kc = 0; kc < Cc; kc += 64) {
        __syncthreads();
        for (int u = d; u < 16*64; u += Dd) { int r = u >> 6, k = u & 63;
            srow[r][k] = X[(size_t)(R0 + r) * Cc + kc + k]; }
        for (int k = 0; k < 64; k++) sW[k][d] = W[(size_t)(kc + k) * Dd + d];
        __syncthreads();
#pragma unroll 8
        for (int k = 0; k < 64; k++) {
            float w = sW[k][d];
#pragma unroll
            for (int r = 0; r < 16; r++) acc[r] += srow[r][k] * w;
        }
    }
    float bb = b[d];
    for (int r = 0; r < 16; r++) OUT[(size_t)(R0 + r) * Dd + d] = acc[r] + bb;
}

// TAGConv linear: OUT = sum_p X_p @ W[p*128:(p+1)*128] + b. grid (n/16, 2), 128 thr.
__global__ void lin_kernel(const float* __restrict__ X0t, const float* __restrict__ X1t,
                           const float* __restrict__ X2t,
                           const float* __restrict__ X0s, const float* __restrict__ X1s,
                           const float* __restrict__ X2s,
                           int nparts, const float* __restrict__ W, const float* __restrict__ b,
                           float* __restrict__ OUTt, float* __restrict__ OUTs) {
    const float* Xs[3];
    float* OUT;
    if (blockIdx.y) { Xs[0] = X0s; Xs[1] = X1s; Xs[2] = X2s; OUT = OUTs; }
    else            { Xs[0] = X0t; Xs[1] = X1t; Xs[2] = X2t; OUT = OUTt; }
    int d = threadIdx.x;
    int R0 = blockIdx.x * 16;
    __shared__ float srow[16][64];
    __shared__ float sW[64][Dd];
    float acc[16];
#pragma unroll
    for (int r = 0; r < 16; r++) acc[r] = 0.f;
    int K = nparts * Dd;
    for (int kc = 0; kc < K; kc += 64) {
        const float* Xp = Xs[kc >> 7];
        int off = kc & 127;
        __syncthreads();
        for (int u = d; u < 16*64; u += Dd) { int r = u >> 6, k = u & 63;
            srow[r][k] = Xp[(size_t)(R0 + r) * Dd + off + k]; }
        for (int k = 0; k < 64; k++) sW[k][d] = W[(size_t)(kc + k) * Dd + d];
        __syncthreads();
#pragma unroll 8
        for (int k = 0; k < 64; k++) {
            float w = sW[k][d];
#pragma unroll
            for (int r = 0; r < 16; r++) acc[r] += srow[r][k] * w;
        }
    }
    float bb = b[d];
    for (int r = 0; r < 16; r++) OUT[(size_t)(R0 + r) * Dd + d] = acc[r] + bb;
}

// rowwise x / sqrt(sum x^2). grid n, 128 thr.
__global__ void l2norm_kernel(float* __restrict__ X) {
    int i = blockIdx.x, t = threadIdx.x;
    float v = X[(size_t)i * Dd + t];
    float s = v * v;
#pragma unroll
    for (int o = 16; o; o >>= 1) s += __shfl_xor_sync(0xffffffffu, s, o);
    __shared__ float ws[4];
    if ((t & 31) == 0) ws[t >> 5] = s;
    __syncthreads();
    float tot = ws[0] + ws[1] + ws[2] + ws[3];
    X[(size_t)i * Dd + t] = v * rsqrtf(tot);
}

// A = (f_et @ f_et^T > 0) with diag forced -> bitmask rows + integer degrees.
// grid (32,32), 256 thr, 64x64 tile, 4x4 per thread.
__global__ void gramA_kernel() {
    __shared__ __align__(16) float sx[64*68];
    __shared__ __align__(16) float sy[64*68];
    __shared__ unsigned sbits[64][2];
    int t = threadIdx.x, tx = t & 15, ty = t >> 4;
    int I0 = blockIdx.y * 64, J0 = blockIdx.x * 64;
    float acc[4][4];
#pragma unroll
    for (int a = 0; a < 4; a++)
#pragma unroll
        for (int c = 0; c < 4; c++) acc[a][c] = 0.f;
    for (int kc = 0; kc < Dd; kc += 64) {
        __syncthreads();
        for (int u = t; u < 4096; u += 256) { int k = u & 63, r = u >> 6;
            sx[k*68 + r] = g_fet[(size_t)(I0 + r) * Dd + kc + k];
            sy[k*68 + r] = g_fet[(size_t)(J0 + r) * Dd + kc + k]; }
        __syncthreads();
#pragma unroll 8
        for (int k = 0; k < 64; k++) {
            float4 a4 = *(const float4*)&sx[k*68 + ty*4];
            float4 b4 = *(const float4*)&sy[k*68 + tx*4];
            acc[0][0] += a4.x*b4.x; acc[0][1] += a4.x*b4.y; acc[0][2] += a4.x*b4.z; acc[0][3] += a4.x*b4.w;
            acc[1][0] += a4.y*b4.x; acc[1][1] += a4.y*b4.y; acc[1][2] += a4.y*b4.z; acc[1][3] += a4.y*b4.w;
            acc[2][0] += a4.z*b4.x; acc[2][1] += a4.z*b4.y; acc[2][2] += a4.z*b4.z; acc[2][3] += a4.z*b4.w;
            acc[3][0] += a4.w*b4.x; acc[3][1] += a4.w*b4.y; acc[3][2] += a4.w*b4.z; acc[3][3] += a4.w*b4.w;
        }
    }
    __syncthreads();
    if (t < 128) ((unsigned*)sbits)[t] = 0;
    __syncthreads();
    int w = tx >> 3, sh = (tx * 4) & 31;
#pragma unroll
    for (int rr = 0; rr < 4; rr++) {
        int i = I0 + ty*4 + rr;
        unsigned nib = 0;
#pragma unroll
        for (int cc = 0; cc < 4; cc++) {
            int j = J0 + tx*4 + cc;
            if (acc[rr][cc] > 0.f || i == j) nib |= 1u << cc;
        }
        if (nib) atomicOr(&sbits[ty*4 + rr][w], nib << sh);
    }
    __syncthreads();
    if (t < 128) {
        int il = t >> 1, ww = t & 1;
        unsigned word = sbits[il][ww];
        g_Abits[(size_t)(I0 + il) * 64 + (J0 >> 5) + ww] = word;
        atomicAdd(&g_deg[I0 + il], __popc(word));
    }
}

__global__ void dinv_kernel() {
    int i = blockIdx.x * blockDim.x + threadIdx.x;
    if (i < Nn) g_dinv[i] = rsqrtf((float)g_deg[i]);
}

// OUT[i,d] = dinv_i * sum_{j: bit(i,j)} dinv_j * H[j,d]
// grid (n/64, 2, 2): x=i-tile, y=d-tile(64), z: 0=teacher 1=student. 256 thr.
__global__ void prop_kernel(const float* __restrict__ Ht, const float* __restrict__ Hs,
                            float* __restrict__ Ot, float* __restrict__ Os,
                            const unsigned* __restrict__ bits, const float* __restrict__ dinv,
                            int n, int nwords) {
    const float* H = blockIdx.z ? Hs : Ht;
    float* O = blockIdx.z ? Os : Ot;
    int t = threadIdx.x, tx = t & 15, ty = t >> 4;
    int I0 = blockIdx.x * 64, D0 = blockIdx.y * 64;
    __shared__ __align__(16) float sh[32*68];
    float acc[4][4];
#pragma unroll
    for (int a = 0; a < 4; a++)
#pragma unroll
        for (int c = 0; c < 4; c++) acc[a][c] = 0.f;
    for (int j0 = 0; j0 < n; j0 += 32) {
        __syncthreads();
        for (int u = t; u < 2048; u += 256) { int dd = u & 63, j = u >> 6;
            sh[j*68 + dd] = H[(size_t)(j0 + j) * Dd + D0 + dd] * dinv[j0 + j]; }
        __syncthreads();
        int wi = j0 >> 5;
        unsigned w0 = bits[(size_t)(I0 + ty*4 + 0) * nwords + wi];
        unsigned w1 = bits[(size_t)(I0 + ty*4 + 1) * nwords + wi];
        unsigned w2 = bits[(size_t)(I0 + ty*4 + 2) * nwords + wi];
        unsigned w3 = bits[(size_t)(I0 + ty*4 + 3) * nwords + wi];
#pragma unroll
        for (int k = 0; k < 32; k++) {
            float4 b4 = *(const float4*)&sh[k*68 + tx*4];
            unsigned m = 1u << k;
            if (w0 & m) { acc[0][0]+=b4.x; acc[0][1]+=b4.y; acc[0][2]+=b4.z; acc[0][3]+=b4.w; }
            if (w1 & m) { acc[1][0]+=b4.x; acc[1][1]+=b4.y; acc[1][2]+=b4.z; acc[1][3]+=b4.w; }
            if (w2 & m) { acc[2][0]+=b4.x; acc[2][1]+=b4.y; acc[2][2]+=b4.z; acc[2][3]+=b4.w; }
            if (w3 & m) { acc[3][0]+=b4.x; acc[3][1]+=b4.y; acc[3][2]+=b4.z; acc[3][3]+=b4.w; }
        }
    }
#pragma unroll
    for (int rr = 0; rr < 4; rr++) {
        int i = I0 + ty*4 + rr;
        float di = dinv[i];
#pragma unroll
        for (int cc = 0; cc < 4; cc++)
            O[(size_t)i * Dd + D0 + tx*4 + cc] = acc[rr][cc] * di;
    }
}

// G = X @ Y^T; per-tile partial row/col sums of exp((G-1)/T).
// grid (n/64 [j tiles], n/64 [i tiles]), 256 thr.
__global__ void gramnce_kernel(const float* __restrict__ X, const float* __restrict__ Y,
                               float* __restrict__ rowp, float* __restrict__ colp, int n) {
    __shared__ __align__(16) float sx[64*68];
    __shared__ __align__(16) float sy[64*68];
    __shared__ float cbuf[16][64];
    int t = threadIdx.x, tx = t & 15, ty = t >> 4;
    int I0 = blockIdx.y * 64, J0 = blockIdx.x * 64;
    float acc[4][4];
#pragma unroll
    for (int a = 0; a < 4; a++)
#pragma unroll
        for (int c = 0; c < 4; c++) acc[a][c] = 0.f;
    for (int kc = 0; kc < Dd; kc += 64) {
        __syncthreads();
        for (int u = t; u < 4096; u += 256) { int k = u & 63, r = u >> 6;
            sx[k*68 + r] = X[(size_t)(I0 + r) * Dd + kc + k];
            sy[k*68 + r] = Y[(size_t)(J0 + r) * Dd + kc + k]; }
        __syncthreads();
#pragma unroll 8
        for (int k = 0; k < 64; k++) {
            float4 a4 = *(const float4*)&sx[k*68 + ty*4];
            float4 b4 = *(const float4*)&sy[k*68 + tx*4];
            acc[0][0] += a4.x*b4.x; acc[0][1] += a4.x*b4.y; acc[0][2] += a4.x*b4.z; acc[0][3] += a4.x*b4.w;
            acc[1][0] += a4.y*b4.x; acc[1][1] += a4.y*b4.y; acc[1][2] += a4.y*b4.z; acc[1][3] += a4.y*b4.w;
            acc[2][0] += a4.z*b4.x; acc[2][1] += a4.z*b4.y; acc[2][2] += a4.z*b4.z; acc[2][3] += a4.z*b4.w;
            acc[3][0] += a4.w*b4.x; acc[3][1] += a4.w*b4.y; acc[3][2] += a4.w*b4.z; acc[3][3] += a4.w*b4.w;
        }
    }
    float e[4][4];
#pragma unroll
    for (int rr = 0; rr < 4; rr++) {
        float rl = 0.f;
#pragma unroll
        for (int cc = 0; cc < 4; cc++) {
            e[rr][cc] = expf((acc[rr][cc] - 1.f) * TINV);
            rl += e[rr][cc];
        }
#pragma unroll
        for (int o = 8; o; o >>= 1) rl += __shfl_xor_sync(0xffffffffu, rl, o);
        if (tx == 0) rowp[(size_t)blockIdx.x * n + I0 + ty*4 + rr] = rl;
    }
#pragma unroll
    for (int cc = 0; cc < 4; cc++)
        cbuf[ty][tx*4 + cc] = e[0][cc] + e[1][cc] + e[2][cc] + e[3][cc];
    __syncthreads();
    if (t < 64) {
        float s = 0.f;
#pragma unroll
        for (int y = 0; y < 16; y++) s += cbuf[y][t];
        colp[(size_t)blockIdx.y * n + J0 + t] = s;
    }
}

// pos[i] = dot(X_i, Y_i). grid n, 128 thr.
__global__ void diag_kernel(const float* __restrict__ X, const float* __restrict__ Y,
                            float* __restrict__ pos) {
    int i = blockIdx.x, t = threadIdx.x;
    float s = X[(size_t)i * Dd + t] * Y[(size_t)i * Dd + t];
#pragma unroll
    for (int o = 16; o; o >>= 1) s += __shfl_xor_sync(0xffffffffu, s, o);
    __shared__ float ws[4];
    if ((t & 31) == 0) ws[t >> 5] = s;
    __syncthreads();
    if (t == 0) pos[i] = ws[0] + ws[1] + ws[2] + ws[3];
}

// scores = sigmoid(f_gt @ W_pool + b_pool). grid Nn, 128 thr.
__global__ void score_kernel(const float* __restrict__ Wp, const float* __restrict__ bp) {
    int i = blockIdx.x, t = threadIdx.x;
    float s = g_fgt[(size_t)i * Dd + t] * Wp[t];
#pragma unroll
    for (int o = 16; o; o >>= 1) s += __shfl_xor_sync(0xffffffffu, s, o);
    __shared__ float ws[4];
    if ((t & 31) == 0) ws[t >> 5] = s;
    __syncthreads();
    if (t == 0) {
        float z = ws[0] + ws[1] + ws[2] + ws[3] + bp[0];
        g_scores[i] = 1.f / (1.f + expf(-z));
    }
}

// rank[i] = #{j: s_j > s_i} + #{j<i: s_j == s_i}. grid Nn, 256 thr.
__global__ void rank_kernel() {
    int i = blockIdx.x, t = threadIdx.x;
    float si = g_scores[i];
    int c = 0;
    for (int j = t; j < Nn; j += 256) {
        float sj = g_scores[j];
        c += (sj > si) || (sj == si && j < i);
    }
    __shared__ int rb[256];
    rb[t] = c; __syncthreads();
    for (int s = 128; s; s >>= 1) { if (t < s) rb[t] += rb[t + s]; __syncthreads(); }
    if (t == 0) g_rank[i] = rb[0];
}

// compact selected (rank < K) in index order. grid Nn, 256 thr.
__global__ void slot_kernel() {
    int i = blockIdx.x;
    if (g_rank[i] >= Kp) return;
    int t = threadIdx.x, c = 0;
    for (int j = t; j < i; j += 256) c += (g_rank[j] < Kp);
    __shared__ int rb[256];
    rb[t] = c; __syncthreads();
    for (int s = 128; s; s >>= 1) { if (t < s) rb[t] += rb[t + s]; __syncthreads(); }
    if (t == 0) { g_selidx[rb[0]] = i; g_selval[rb[0]] = g_scores[i]; }
}

// new_h = f_g[idx] * val. grid Kp, 128 thr.
__global__ void gather_kernel() {
    int p = blockIdx.x, d = threadIdx.x;
    int i = g_selidx[p];
    float v = g_selval[p];
    g_nht[(size_t)p * Dd + d] = g_fgt[(size_t)i * Dd + d] * v;
    g_nhs[(size_t)p * Dd + d] = g_fgs[(size_t)i * Dd + d] * v;
}

// sub[p][q] = rows idx_p, idx_q of A intersect (A symmetric -> 2-hop). grid (16,16), 256 thr.
__global__ void subbits_kernel() {
    __shared__ unsigned pr[64*65], qr[64*65];
    __shared__ unsigned pb[64][2];
    int t = threadIdx.x;
    int P0 = blockIdx.y * 64, Q0 = blockIdx.x * 64;
    for (int u = t; u < 4096; u += 256) { int w = u & 63, r = u >> 6;
        pr[r*65 + w] = g_Abits[(size_t)g_selidx[P0 + r] * 64 + w];
        qr[r*65 + w] = g_Abits[(size_t)g_selidx[Q0 + r] * 64 + w]; }
    if (t < 128) ((unsigned*)pb)[t] = 0;
    __syncthreads();
    int p = t >> 2, qb = t & 3;
    unsigned res = 0;
    for (int qq = 0; qq < 16; qq++) {
        int q = qb * 16 + qq;
        unsigned any = 0;
#pragma unroll 16
        for (int w = 0; w < 64; w++) any |= pr[p*65 + w] & qr[q*65 + w];
        res |= (any ? 1u : 0u) << qq;
    }
    atomicOr(&pb[p][qb >> 1], res << ((qb & 1) * 16));
    __syncthreads();
    if (t < 128) {
        int pl = t >> 1, w = t & 1;
        g_Pbits[(size_t)(P0 + pl) * 32 + (Q0 >> 5) + w] = pb[pl][w];
    }
}

__global__ void dinvp_kernel() {
    int p = blockIdx.x * blockDim.x + threadIdx.x;
    if (p >= Kp) return;
    int dg = 0;
    for (int w = 0; w < 32; w++) dg += __popc(g_Pbits[(size_t)p * 32 + w]);
    g_dinvp[p] = rsqrtf((float)dg);
}

// terms[i] = log(rowsum) + log(colsum) + 2*(1-pos)/T
__global__ void terms_kernel(const float* __restrict__ rowp, const float* __restrict__ colp,
                             const float* __restrict__ pos, float* __restrict__ terms,
                             int n, int ntiles) {
    int i = blockIdx.x * blockDim.x + threadIdx.x;
    if (i >= n) return;
    float rs = 0.f, cs = 0.f;
    for (int k = 0; k < ntiles; k++) { rs += rowp[(size_t)k * n + i]; cs += colp[(size_t)k * n + i]; }
    terms[i] = logf(rs) + logf(cs) + 2.f * (1.f - pos[i]) * TINV;
}

__global__ void final_kernel(float* __restrict__ out) {
    int t = threadIdx.x;
    float s1 = 0.f, s2 = 0.f;
    for (int i = t; i < Nn; i += 256) s1 += g_terms1[i];
    for (int i = t; i < Kp; i += 256) s2 += g_terms2[i];
    __shared__ float r1[256], r2[256];
    r1[t] = s1; r2[t] = s2; __syncthreads();
    for (int s = 128; s; s >>= 1) { if (t < s) { r1[t] += r1[t + s]; r2[t] += r2[t + s]; } __syncthreads(); }
    if (t == 0) out[0] = r1[0] / (float)Nn + r2[0] / (float)Kp;
}

// ----------------- launch -----------------

template <typename T> static T* sym(const T& s) {
    void* p = nullptr;
    cudaGetSymbolAddress(&p, s);
    return (T*)p;
}

extern "C" void kernel_launch(void* const* d_in, const int* in_sizes, int n_in,
                              void* d_out, int out_size) {
    const float* fs  = (const float*)d_in[0];
    const float* ft  = (const float*)d_in[1];
    const float* We  = (const float*)d_in[2];
    const float* be  = (const float*)d_in[3];
    const float* Wg  = (const float*)d_in[4];
    const float* bg  = (const float*)d_in[5];
    const float* Wp  = (const float*)d_in[6];
    const float* bp  = (const float*)d_in[7];
    const float* Wgp = (const float*)d_in[8];
    const float* bgp = (const float*)d_in[9];
    float* out = (float*)d_out;

    float* fes = (float*)sym(g_fes);   float* fet = (float*)sym(g_fet);
    float* h1t = (float*)sym(g_h1t);   float* h1s = (float*)sym(g_h1s);
    float* h2t = (float*)sym(g_h2t);   float* h2s = (float*)sym(g_h2s);
    float* fgt = (float*)sym(g_fgt);   float* fgs = (float*)sym(g_fgs);
    float* nht = (float*)sym(g_nht);   float* nhs = (float*)sym(g_nhs);
    float* ph1t = (float*)sym(g_ph1t); float* ph1s = (float*)sym(g_ph1s);
    float* fpt = (float*)sym(g_fpt);   float* fps = (float*)sym(g_fps);
    float* dinv = (float*)sym(g_dinv); float* dinvp = (float*)sym(g_dinvp);
    unsigned* Ab = (unsigned*)sym(g_Abits);
    unsigned* Pb = (unsigned*)sym(g_Pbits);
    float* rowp1 = (float*)sym(g_rowp1); float* colp1 = (float*)sym(g_colp1);
    float* rowp2 = (float*)sym(g_rowp2); float* colp2 = (float*)sym(g_colp2);
    float* pos1 = (float*)sym(g_pos1);   float* pos2 = (float*)sym(g_pos2);
    float* terms1 = (float*)sym(g_terms1); float* terms2 = (float*)sym(g_terms2);

    zero_deg_kernel<<<8, 256>>>();
    embed_kernel<<<dim3(Nn/16, 2), 128>>>(fs, ft, We, be);
    l2norm_kernel<<<Nn, 128>>>(fes);
    l2norm_kernel<<<Nn, 128>>>(fet);
    gramA_kernel<<<dim3(32, 32), 256>>>();
    dinv_kernel<<<8, 256>>>();
    prop_kernel<<<dim3(32, 2, 2), 256>>>(fet, fes, h1t, h1s, Ab, dinv, Nn, 64);
    prop_kernel<<<dim3(32, 2, 2), 256>>>(h1t, h1s, h2t, h2s, Ab, dinv, Nn, 64);
    lin_kernel<<<dim3(Nn/16, 2), 128>>>(fet, h1t, h2t, fes, h1s, h2s, 3, Wg, bg, fgt, fgs);
    l2norm_kernel<<<Nn, 128>>>(fgt);
    l2norm_kernel<<<Nn, 128>>>(fgs);
    gramnce_kernel<<<dim3(32, 32), 256>>>(fgt, fgs, rowp1, colp1, Nn);
    diag_kernel<<<Nn, 128>>>(fgt, fgs, pos1);
    score_kernel<<<Nn, 128>>>(Wp, bp);
    rank_kernel<<<Nn, 256>>>();
    slot_kernel<<<Nn, 256>>>();
    gather_kernel<<<Kp, 128>>>();
    subbits_kernel<<<dim3(16, 16), 256>>>();
    dinvp_kernel<<<4, 256>>>();
    prop_kernel<<<dim3(16, 2, 2), 256>>>(nht, nhs, ph1t, ph1s, Pb, dinvp, Kp, 32);
    lin_kernel<<<dim3(Kp/16, 2), 128>>>(nht, ph1t, nullptr, nhs, ph1s, nullptr, 2, Wgp, bgp, fpt, fps);
    l2norm_kernel<<<Kp, 128>>>(fpt);
    l2norm_kernel<<<Kp, 128>>>(fps);
    gramnce_kernel<<<dim3(16, 16), 256>>>(fpt, fps, rowp2, colp2, Kp);
    diag_kernel<<<Kp, 128>>>(fpt, fps, pos2);
    terms_kernel<<<8, 256>>>(rowp1, colp1, pos1, terms1, Nn, 32);
    terms_kernel<<<4, 256>>>(rowp2, colp2, pos2, terms2, Kp, 16);
    final_kernel<<<1, 256>>>(out);
}

// round 5
// speedup vs baseline: 1.2979x; 1.2979x over previous
#include <cuda_runtime.h>
#include <cstdint>

#define Nn 2048
#define Dd 128
#define Cc 512
#define Kp 1024
#define TINV 14.285714285714286f

// ----------------- scratch (device globals; allocation-free) -----------------
__device__ float    g_fes[Nn*Dd], g_fet[Nn*Dd];
__device__ unsigned g_Abits[Nn*64];
__device__ float    g_dinv[Nn];
__device__ float    g_h1t[Nn*Dd], g_h1s[Nn*Dd], g_h2t[Nn*Dd], g_h2s[Nn*Dd];
__device__ float    g_fgt[Nn*Dd], g_fgs[Nn*Dd];
__device__ float    g_rowp1[32*Nn], g_colp1[32*Nn];
__device__ float    g_pos1[Nn];
__device__ float    g_scores[Nn];
__device__ int      g_selidx[Kp];
__device__ float    g_selval[Kp];
__device__ float    g_nht[Kp*Dd], g_nhs[Kp*Dd];
__device__ unsigned g_Pbits[Kp*32];
__device__ float    g_dinvp[Kp];
__device__ float    g_ph1t[Kp*Dd], g_ph1s[Kp*Dd];
__device__ float    g_fpt[Kp*Dd], g_fps[Kp*Dd];
__device__ float    g_rowp2[16*Kp], g_colp2[16*Kp];
__device__ float    g_pos2[Kp];

// ----------------- kernels -----------------

// OUT[16 rows] = l2norm(X @ W_embed + b). grid (Nn/16, 2): y=0 fs->fes, y=1 ft->fet. 128 thr.
__global__ void embed_kernel(const float* __restrict__ fs, const float* __restrict__ ft,
                             const float* __restrict__ W, const float* __restrict__ b) {
    const float* X = blockIdx.y ? ft : fs;
    float* OUT = blockIdx.y ? g_fet : g_fes;
    int d = threadIdx.x;
    int R0 = blockIdx.x * 16;
    __shared__ __align__(16) float srow[16][64];
    __shared__ float sW[64][Dd];
    __shared__ float sred[16][132];
    __shared__ float sscale[16];
    float acc[16];
#pragma unroll
    for (int r = 0; r < 16; r++) acc[r] = 0.f;
    for (int kc = 0; kc < Cc; kc += 64) {
        __syncthreads();
        for (int u = d; u < 256; u += Dd) { int r = u >> 4, kq = u & 15;
            ((float4*)srow[r])[kq] = *(const float4*)&X[(size_t)(R0 + r) * Cc + kc + kq*4]; }
        for (int k = 0; k < 64; k++) sW[k][d] = W[(size_t)(kc + k) * Dd + d];
        __syncthreads();
#pragma unroll 4
        for (int k4 = 0; k4 < 16; k4++) {
            float w0 = sW[k4*4+0][d], w1 = sW[k4*4+1][d], w2 = sW[k4*4+2][d], w3 = sW[k4*4+3][d];
#pragma unroll
            for (int r = 0; r < 16; r++) {
                float4 s4 = ((float4*)srow[r])[k4];
                acc[r] += s4.x*w0; acc[r] += s4.y*w1; acc[r] += s4.z*w2; acc[r] += s4.w*w3;
            }
        }
    }
    float bb = b[d];
#pragma unroll
    for (int r = 0; r < 16; r++) sred[r][d] = acc[r] + bb;
    __syncthreads();
    int lane = d & 31, w = d >> 5;
#pragma unroll
    for (int m = 0; m < 4; m++) {
        int r = w*4 + m;
        float x0 = sred[r][lane], x1 = sred[r][lane+32], x2 = sred[r][lane+64], x3 = sred[r][lane+96];
        float s = x0*x0 + x1*x1 + x2*x2 + x3*x3;
#pragma unroll
        for (int o = 16; o; o >>= 1) s += __shfl_xor_sync(0xffffffffu, s, o);
        if (lane == 0) sscale[r] = rsqrtf(s);
    }
    __syncthreads();
#pragma unroll
    for (int r = 0; r < 16; r++) OUT[(size_t)(R0 + r) * Dd + d] = sred[r][d] * sscale[r];
}

// TAGConv linear + l2norm (+ optional scores on teacher branch). grid (n/16, 2), 128 thr.
__global__ void lin_kernel(const float* __restrict__ X0t, const float* __restrict__ X1t,
                           const float* __restrict__ X2t,
                           const float* __restrict__ X0s, const float* __restrict__ X1s,
                           const float* __restrict__ X2s,
                           int nparts, const float* __restrict__ W, const float* __restrict__ b,
                           float* __restrict__ OUTt, float* __restrict__ OUTs,
                           const float* __restrict__ Wp, const float* __restrict__ bp,
                           int do_score) {
    const float* Xs[3];
    float* OUT;
    if (blockIdx.y) { Xs[0] = X0s; Xs[1] = X1s; Xs[2] = X2s; OUT = OUTs; }
    else            { Xs[0] = X0t; Xs[1] = X1t; Xs[2] = X2t; OUT = OUTt; }
    int d = threadIdx.x;
    int R0 = blockIdx.x * 16;
    __shared__ __align__(16) float srow[16][64];
    __shared__ float sW[64][Dd];
    __shared__ float sred[16][132];
    __shared__ float sscale[16];
    float acc[16];
#pragma unroll
    for (int r = 0; r < 16; r++) acc[r] = 0.f;
    int K = nparts * Dd;
    for (int kc = 0; kc < K; kc += 64) {
        const float* Xp = Xs[kc >> 7];
        int off = kc & 127;
        __syncthreads();
        for (int u = d; u < 256; u += Dd) { int r = u >> 4, kq = u & 15;
            ((float4*)srow[r])[kq] = *(const float4*)&Xp[(size_t)(R0 + r) * Dd + off + kq*4]; }
        for (int k = 0; k < 64; k++) sW[k][d] = W[(size_t)(kc + k) * Dd + d];
        __syncthreads();
#pragma unroll 4
        for (int k4 = 0; k4 < 16; k4++) {
            float w0 = sW[k4*4+0][d], w1 = sW[k4*4+1][d], w2 = sW[k4*4+2][d], w3 = sW[k4*4+3][d];
#pragma unroll
            for (int r = 0; r < 16; r++) {
                float4 s4 = ((float4*)srow[r])[k4];
                acc[r] += s4.x*w0; acc[r] += s4.y*w1; acc[r] += s4.z*w2; acc[r] += s4.w*w3;
            }
        }
    }
    float bb = b[d];
#pragma unroll
    for (int r = 0; r < 16; r++) sred[r][d] = acc[r] + bb;
    __syncthreads();
    int lane = d & 31, w = d >> 5;
    bool sc = do_score && (blockIdx.y == 0);
    float wp0 = 0.f, wp1 = 0.f, wp2 = 0.f, wp3 = 0.f;
    if (sc) { wp0 = Wp[lane]; wp1 = Wp[lane+32]; wp2 = Wp[lane+64]; wp3 = Wp[lane+96]; }
#pragma unroll
    for (int m = 0; m < 4; m++) {
        int r = w*4 + m;
        float x0 = sred[r][lane], x1 = sred[r][lane+32], x2 = sred[r][lane+64], x3 = sred[r][lane+96];
        float s = x0*x0 + x1*x1 + x2*x2 + x3*x3;
        float sp = x0*wp0 + x1*wp1 + x2*wp2 + x3*wp3;
#pragma unroll
        for (int o = 16; o; o >>= 1) { s += __shfl_xor_sync(0xffffffffu, s, o);
                                       sp += __shfl_xor_sync(0xffffffffu, sp, o); }
        if (lane == 0) {
            float scale = rsqrtf(s);
            sscale[r] = scale;
            if (sc) g_scores[R0 + r] = 1.f / (1.f + expf(-(sp * scale + bp[0])));
        }
    }
    __syncthreads();
#pragma unroll
    for (int r = 0; r < 16; r++) OUT[(size_t)(R0 + r) * Dd + d] = sred[r][d] * sscale[r];
}

// A = (fet @ fet^T > 0) with forced diag -> bitmask. Symmetric: lower-triangle tiles, mirrored.
// grid 528 (= 32*33/2), 256 thr, 64x64 tile, 4x4 per thread.
__global__ void gramA_kernel() {
    int l = blockIdx.x;
    int by = (int)((sqrtf(8.f * l + 1.f) - 1.f) * 0.5f);
    while ((by + 1) * (by + 2) / 2 <= l) by++;
    while (by * (by + 1) / 2 > l) by--;
    int bx = l - by * (by + 1) / 2;
    int I0 = by * 64, J0 = bx * 64;
    __shared__ __align__(16) float sx[64*68];
    __shared__ __align__(16) float sy[64*68];
    __shared__ unsigned sbits[64][2], tbits[64][2];
    int t = threadIdx.x, tx = t & 15, ty = t >> 4;
    float acc[4][4];
#pragma unroll
    for (int a = 0; a < 4; a++)
#pragma unroll
        for (int c = 0; c < 4; c++) acc[a][c] = 0.f;
    for (int kc = 0; kc < Dd; kc += 64) {
        __syncthreads();
        for (int u = t; u < 4096; u += 256) { int k = u & 63, r = u >> 6;
            sx[k*68 + r] = g_fet[(size_t)(I0 + r) * Dd + kc + k];
            sy[k*68 + r] = g_fet[(size_t)(J0 + r) * Dd + kc + k]; }
        __syncthreads();
#pragma unroll 8
        for (int k = 0; k < 64; k++) {
            float4 a4 = *(const float4*)&sx[k*68 + ty*4];
            float4 b4 = *(const float4*)&sy[k*68 + tx*4];
            acc[0][0] += a4.x*b4.x; acc[0][1] += a4.x*b4.y; acc[0][2] += a4.x*b4.z; acc[0][3] += a4.x*b4.w;
            acc[1][0] += a4.y*b4.x; acc[1][1] += a4.y*b4.y; acc[1][2] += a4.y*b4.z; acc[1][3] += a4.y*b4.w;
            acc[2][0] += a4.z*b4.x; acc[2][1] += a4.z*b4.y; acc[2][2] += a4.z*b4.z; acc[2][3] += a4.z*b4.w;
            acc[3][0] += a4.w*b4.x; acc[3][1] += a4.w*b4.y; acc[3][2] += a4.w*b4.z; acc[3][3] += a4.w*b4.w;
        }
    }
    __syncthreads();
    if (t < 128) { ((unsigned*)sbits)[t] = 0; ((unsigned*)tbits)[t] = 0; }
    __syncthreads();
    int wj = (tx * 4) >> 5, shj = (tx * 4) & 31;
    int wi = (ty * 4) >> 5, shi = (ty * 4) & 31;
#pragma unroll
    for (int rr = 0; rr < 4; rr++) {
        int i = I0 + ty*4 + rr;
        unsigned nib = 0;
#pragma unroll
        for (int cc = 0; cc < 4; cc++) {
            int j = J0 + tx*4 + cc;
            if (acc[rr][cc] > 0.f || i == j) nib |= 1u << cc;
        }
        if (nib) atomicOr(&sbits[ty*4 + rr][wj], nib << shj);
    }
#pragma unroll
    for (int cc = 0; cc < 4; cc++) {
        int j = J0 + tx*4 + cc;
        unsigned nib = 0;
#pragma unroll
        for (int rr = 0; rr < 4; rr++) {
            int i = I0 + ty*4 + rr;
            if (acc[rr][cc] > 0.f || i == j) nib |= 1u << rr;
        }
        if (nib) atomicOr(&tbits[tx*4 + cc][wi], nib << shi);
    }
    __syncthreads();
    if (t < 128) {
        int il = t >> 1, ww = t & 1;
        g_Abits[(size_t)(I0 + il) * 64 + (J0 >> 5) + ww] = sbits[il][ww];
        g_Abits[(size_t)(J0 + il) * 64 + (I0 >> 5) + ww] = tbits[il][ww];
    }
}

// dinv[i] = rsqrt(popcount of A row i)
__global__ void dinv_kernel() {
    int i = blockIdx.x * blockDim.x + threadIdx.x;
    if (i >= Nn) return;
    const uint4* p = (const uint4*)&g_Abits[(size_t)i * 64];
    int dg = 0;
#pragma unroll
    for (int w = 0; w < 16; w++) { uint4 v = p[w];
        dg += __popc(v.x) + __popc(v.y) + __popc(v.z) + __popc(v.w); }
    g_dinv[i] = rsqrtf((float)dg);
}

// OUT[i,d] = dinv_i * sum_{j: bit(i,j)} dinv_j * H[j,d]. grid (n/64, 2, z:t/s), 256 thr.
__global__ void prop_kernel(const float* __restrict__ Ht, const float* __restrict__ Hs,
                            float* __restrict__ Ot, float* __restrict__ Os,
                            const unsigned* __restrict__ bits, const float* __restrict__ dinv,
                            int n, int nwords) {
    const float* H = blockIdx.z ? Hs : Ht;
    float* O = blockIdx.z ? Os : Ot;
    int t = threadIdx.x, tx = t & 15, ty = t >> 4;
    int I0 = blockIdx.x * 64, D0 = blockIdx.y * 64;
    int r0 = I0 + ty * 4;
    __shared__ __align__(16) float sh[32*72];
    float acc[4][4];
#pragma unroll
    for (int a = 0; a < 4; a++)
#pragma unroll
        for (int c = 0; c < 4; c++) acc[a][c] = 0.f;
    for (int j0 = 0; j0 < n; j0 += 32) {
        __syncthreads();
        for (int u = t; u < 512; u += 256) {
            int j = u >> 4, dq = u & 15;
            float4 v = *(const float4*)&H[(size_t)(j0 + j) * Dd + D0 + dq*4];
            float di = dinv[j0 + j];
            v.x *= di; v.y *= di; v.z *= di; v.w *= di;
            *(float4*)&sh[j*72 + dq*4] = v;
        }
        __syncthreads();
        int wi = j0 >> 5;
        unsigned w0 = bits[(size_t)(r0 + 0) * nwords + wi];
        unsigned w1 = bits[(size_t)(r0 + 1) * nwords + wi];
        unsigned w2 = bits[(size_t)(r0 + 2) * nwords + wi];
        unsigned w3 = bits[(size_t)(r0 + 3) * nwords + wi];
#pragma unroll
        for (int k = 0; k < 32; k++) {
            float4 b4 = *(const float4*)&sh[k*72 + tx*4];
            unsigned m = 1u << k;
            if (w0 & m) { acc[0][0]+=b4.x; acc[0][1]+=b4.y; acc[0][2]+=b4.z; acc[0][3]+=b4.w; }
            if (w1 & m) { acc[1][0]+=b4.x; acc[1][1]+=b4.y; acc[1][2]+=b4.z; acc[1][3]+=b4.w; }
            if (w2 & m) { acc[2][0]+=b4.x; acc[2][1]+=b4.y; acc[2][2]+=b4.z; acc[2][3]+=b4.w; }
            if (w3 & m) { acc[3][0]+=b4.x; acc[3][1]+=b4.y; acc[3][2]+=b4.z; acc[3][3]+=b4.w; }
        }
    }
#pragma unroll
    for (int rr = 0; rr < 4; rr++) {
        float di = dinv[r0 + rr];
        float4 o = make_float4(acc[rr][0]*di, acc[rr][1]*di, acc[rr][2]*di, acc[rr][3]*di);
        *(float4*)&O[(size_t)(r0 + rr) * Dd + D0 + tx*4] = o;
    }
}

// G = X @ Y^T; per-tile partial row/col sums of exp((G-1)/T); diag tiles emit pos.
__global__ void gramnce_kernel(const float* __restrict__ X, const float* __restrict__ Y,
                               float* __restrict__ rowp, float* __restrict__ colp,
                               float* __restrict__ pos, int n) {
    __shared__ __align__(16) float sx[64*68];
    __shared__ __align__(16) float sy[64*68];
    __shared__ float cbuf[16][64];
    int t = threadIdx.x, tx = t & 15, ty = t >> 4;
    int I0 = blockIdx.y * 64, J0 = blockIdx.x * 64;
    float acc[4][4];
#pragma unroll
    for (int a = 0; a < 4; a++)
#pragma unroll
        for (int c = 0; c < 4; c++) acc[a][c] = 0.f;
    for (int kc = 0; kc < Dd; kc += 64) {
        __syncthreads();
        for (int u = t; u < 4096; u += 256) { int k = u & 63, r = u >> 6;
            sx[k*68 + r] = X[(size_t)(I0 + r) * Dd + kc + k];
            sy[k*68 + r] = Y[(size_t)(J0 + r) * Dd + kc + k]; }
        __syncthreads();
#pragma unroll 8
        for (int k = 0; k < 64; k++) {
            float4 a4 = *(const float4*)&sx[k*68 + ty*4];
            float4 b4 = *(const float4*)&sy[k*68 + tx*4];
            acc[0][0] += a4.x*b4.x; acc[0][1] += a4.x*b4.y; acc[0][2] += a4.x*b4.z; acc[0][3] += a4.x*b4.w;
            acc[1][0] += a4.y*b4.x; acc[1][1] += a4.y*b4.y; acc[1][2] += a4.y*b4.z; acc[1][3] += a4.y*b4.w;
            acc[2][0] += a4.z*b4.x; acc[2][1] += a4.z*b4.y; acc[2][2] += a4.z*b4.z; acc[2][3] += a4.z*b4.w;
            acc[3][0] += a4.w*b4.x; acc[3][1] += a4.w*b4.y; acc[3][2] += a4.w*b4.z; acc[3][3] += a4.w*b4.w;
        }
    }
    if (I0 == J0) {
#pragma unroll
        for (int rr = 0; rr < 4; rr++) {
            int dd = ty*4 + rr - tx*4;
            if (dd >= 0 && dd < 4) pos[I0 + ty*4 + rr] = acc[rr][dd];
        }
    }
    float e[4][4];
#pragma unroll
    for (int rr = 0; rr < 4; rr++) {
        float rl = 0.f;
#pragma unroll
        for (int cc = 0; cc < 4; cc++) {
            e[rr][cc] = expf((acc[rr][cc] - 1.f) * TINV);
            rl += e[rr][cc];
        }
#pragma unroll
        for (int o = 8; o; o >>= 1) rl += __shfl_xor_sync(0xffffffffu, rl, o);
        if (tx == 0) rowp[(size_t)blockIdx.x * n + I0 + ty*4 + rr] = rl;
    }
#pragma unroll
    for (int cc = 0; cc < 4; cc++)
        cbuf[ty][tx*4 + cc] = e[0][cc] + e[1][cc] + e[2][cc] + e[3][cc];
    __syncthreads();
    if (t < 64) {
        float s = 0.f;
#pragma unroll
        for (int y = 0; y < 16; y++) s += cbuf[y][t];
        colp[(size_t)blockIdx.y * n + J0 + t] = s;
    }
}

// rank[i] = #{j: s_j > s_i} + #{j<i: s_j == s_i}; rank is a permutation -> direct slot write.
__global__ void rank_kernel() {
    int i = blockIdx.x, t = threadIdx.x;
    float si = g_scores[i];
    int c = 0;
    for (int j = t; j < Nn; j += 256) {
        float sj = g_scores[j];
        c += (sj > si) || (sj == si && j < i);
    }
    __shared__ int rb[256];
    rb[t] = c; __syncthreads();
    for (int s = 128; s; s >>= 1) { if (t < s) rb[t] += rb[t + s]; __syncthreads(); }
    if (t == 0) {
        int r = rb[0];
        if (r < Kp) { g_selidx[r] = i; g_selval[r] = si; }
    }
}

// new_h = f_g[idx] * val. grid Kp, 128 thr.
__global__ void gather_kernel() {
    int p = blockIdx.x, d = threadIdx.x;
    int i = g_selidx[p];
    float v = g_selval[p];
    g_nht[(size_t)p * Dd + d] = g_fgt[(size_t)i * Dd + d] * v;
    g_nhs[(size_t)p * Dd + d] = g_fgs[(size_t)i * Dd + d] * v;
}

// sub[p][q] = rows idx_p, idx_q of A intersect. grid (16,16), 256 thr. uint4 loads.
__global__ void subbits_kernel() {
    __shared__ __align__(16) unsigned pr[64*68];
    __shared__ __align__(16) unsigned qr[64*68];
    __shared__ unsigned pb[64][2];
    int t = threadIdx.x;
    int P0 = blockIdx.y * 64, Q0 = blockIdx.x * 64;
    for (int u = t; u < 1024; u += 256) {
        int r = u >> 4, w4 = u & 15;
        *(uint4*)&pr[r*68 + w4*4] = *(const uint4*)&g_Abits[(size_t)g_selidx[P0 + r] * 64 + w4*4];
        *(uint4*)&qr[r*68 + w4*4] = *(const uint4*)&g_Abits[(size_t)g_selidx[Q0 + r] * 64 + w4*4];
    }
    if (t < 128) ((unsigned*)pb)[t] = 0;
    __syncthreads();
    int p = t >> 2, qb = t & 3;
    unsigned anyv[16];
#pragma unroll
    for (int qq = 0; qq < 16; qq++) anyv[qq] = 0;
    for (int w4 = 0; w4 < 16; w4++) {
        uint4 a = *(const uint4*)&pr[p*68 + w4*4];
#pragma unroll
        for (int qq = 0; qq < 16; qq++) {
            uint4 bv = *(const uint4*)&qr[(qb*16 + qq)*68 + w4*4];
            anyv[qq] |= (a.x & bv.x) | (a.y & bv.y) | (a.z & bv.z) | (a.w & bv.w);
        }
    }
    unsigned res = 0;
#pragma unroll
    for (int qq = 0; qq < 16; qq++) res |= (anyv[qq] ? 1u : 0u) << qq;
    atomicOr(&pb[p][qb >> 1], res << ((qb & 1) * 16));
    __syncthreads();
    if (t < 128) g_Pbits[(size_t)(P0 + (t >> 1)) * 32 + (Q0 >> 5) + (t & 1)] = pb[t >> 1][t & 1];
}

__global__ void dinvp_kernel() {
    int p = blockIdx.x * blockDim.x + threadIdx.x;
    if (p >= Kp) return;
    const uint4* q = (const uint4*)&g_Pbits[(size_t)p * 32];
    int dg = 0;
#pragma unroll
    for (int w = 0; w < 8; w++) { uint4 v = q[w];
        dg += __popc(v.x) + __popc(v.y) + __popc(v.z) + __popc(v.w); }
    g_dinvp[p] = rsqrtf((float)dg);
}

// terms + final reduce, single block 1024 thr.
__global__ void final_kernel(float* __restrict__ out) {
    int t = threadIdx.x;
    float s1 = 0.f, s2 = 0.f;
    for (int i = t; i < Nn; i += 1024) {
        float rs = 0.f, cs = 0.f;
        for (int k = 0; k < 32; k++) { rs += g_rowp1[(size_t)k * Nn + i]; cs += g_colp1[(size_t)k * Nn + i]; }
        s1 += logf(rs) + logf(cs) + 2.f * (1.f - g_pos1[i]) * TINV;
    }
    for (int i = t; i < Kp; i += 1024) {
        float rs = 0.f, cs = 0.f;
        for (int k = 0; k < 16; k++) { rs += g_rowp2[(size_t)k * Kp + i]; cs += g_colp2[(size_t)k * Kp + i]; }
        s2 += logf(rs) + logf(cs) + 2.f * (1.f - g_pos2[i]) * TINV;
    }
    __shared__ float r1[1024], r2[1024];
    r1[t] = s1; r2[t] = s2; __syncthreads();
    for (int s = 512; s; s >>= 1) { if (t < s) { r1[t] += r1[t + s]; r2[t] += r2[t + s]; } __syncthreads(); }
    if (t == 0) out[0] = r1[0] / (float)Nn + r2[0] / (float)Kp;
}

// ----------------- launch -----------------

template <typename T> static T* sym(const T& s) {
    void* p = nullptr;
    cudaGetSymbolAddress(&p, s);
    return (T*)p;
}

extern "C" void kernel_launch(void* const* d_in, const int* in_sizes, int n_in,
                              void* d_out, int out_size) {
    const float* fs  = (const float*)d_in[0];
    const float* ft  = (const float*)d_in[1];
    const float* We  = (const float*)d_in[2];
    const float* be  = (const float*)d_in[3];
    const float* Wg  = (const float*)d_in[4];
    const float* bg  = (const float*)d_in[5];
    const float* Wp  = (const float*)d_in[6];
    const float* bp  = (const float*)d_in[7];
    const float* Wgp = (const float*)d_in[8];
    const float* bgp = (const float*)d_in[9];
    float* out = (float*)d_out;

    float* fes = (float*)sym(g_fes);   float* fet = (float*)sym(g_fet);
    float* h1t = (float*)sym(g_h1t);   float* h1s = (float*)sym(g_h1s);
    float* h2t = (float*)sym(g_h2t);   float* h2s = (float*)sym(g_h2s);
    float* fgt = (float*)sym(g_fgt);   float* fgs = (float*)sym(g_fgs);
    float* nht = (float*)sym(g_nht);   float* nhs = (float*)sym(g_nhs);
    float* ph1t = (float*)sym(g_ph1t); float* ph1s = (float*)sym(g_ph1s);
    float* fpt = (float*)sym(g_fpt);   float* fps = (float*)sym(g_fps);
    float* dinv = (float*)sym(g_dinv); float* dinvp = (float*)sym(g_dinvp);
    unsigned* Ab = (unsigned*)sym(g_Abits);
    unsigned* Pb = (unsigned*)sym(g_Pbits);
    float* rowp1 = (float*)sym(g_rowp1); float* colp1 = (float*)sym(g_colp1);
    float* rowp2 = (float*)sym(g_rowp2); float* colp2 = (float*)sym(g_colp2);
    float* pos1 = (float*)sym(g_pos1);   float* pos2 = (float*)sym(g_pos2);

    embed_kernel<<<dim3(Nn/16, 2), 128>>>(fs, ft, We, be);
    gramA_kernel<<<528, 256>>>();
    dinv_kernel<<<8, 256>>>();
    prop_kernel<<<dim3(32, 2, 2), 256>>>(fet, fes, h1t, h1s, Ab, dinv, Nn, 64);
    prop_kernel<<<dim3(32, 2, 2), 256>>>(h1t, h1s, h2t, h2s, Ab, dinv, Nn, 64);
    lin_kernel<<<dim3(Nn/16, 2), 128>>>(fet, h1t, h2t, fes, h1s, h2s, 3, Wg, bg, fgt, fgs, Wp, bp, 1);
    gramnce_kernel<<<dim3(32, 32), 256>>>(fgt, fgs, rowp1, colp1, pos1, Nn);
    rank_kernel<<<Nn, 256>>>();
    gather_kernel<<<Kp, 128>>>();
    subbits_kernel<<<dim3(16, 16), 256>>>();
    dinvp_kernel<<<4, 256>>>();
    prop_kernel<<<dim3(16, 2, 2), 256>>>(nht, nhs, ph1t, ph1s, Pb, dinvp, Kp, 32);
    lin_kernel<<<dim3(Kp/16, 2), 128>>>(nht, ph1t, nullptr, nhs, ph1s, nullptr, 2, Wgp, bgp, fpt, fps, nullptr, nullptr, 0);
    gramnce_kernel<<<dim3(16, 16), 256>>>(fpt, fps, rowp2, colp2, pos2, Kp);
    final_kernel<<<1, 1024>>>(out);
}

// round 8
// speedup vs baseline: 1.6527x; 1.2734x over previous
#include <cuda_runtime.h>
#include <cstdint>

#define Nn 2048
#define Dd 128
#define Cc 512
#define Kp 1024
#define TINV 14.285714285714286f

// ----------------- scratch (device globals; allocation-free) -----------------
__device__ float    g_fes[Nn*Dd], g_fet[Nn*Dd];
__device__ unsigned g_Abits[Nn*64];
__device__ float    g_dinv[Nn];
__device__ float    g_h1t[Nn*Dd], g_h1s[Nn*Dd], g_h2t[Nn*Dd], g_h2s[Nn*Dd];
__device__ float    g_fgt[Nn*Dd], g_fgs[Nn*Dd];
__device__ float    g_pp[2*8*Nn*Dd];          // 16 MB partial-prop scratch
__device__ float    g_rowp1[32*Nn], g_colp1[32*Nn];
__device__ float    g_pos1[Nn];
__device__ float    g_scores[Nn];
__device__ int      g_selidx[Kp];
__device__ float    g_selval[Kp];
__device__ float    g_nht[Kp*Dd], g_nhs[Kp*Dd];
__device__ unsigned g_Pbits[Kp*32];
__device__ float    g_dinvp[Kp];
__device__ float    g_ph1t[Kp*Dd], g_ph1s[Kp*Dd];
__device__ float    g_fpt[Kp*Dd], g_fps[Kp*Dd];
__device__ float    g_rowp2[16*Kp], g_colp2[16*Kp];
__device__ float    g_pos2[Kp];

// ----------------- kernels -----------------

// OUT[16 rows] = l2norm(X @ W_embed + b). grid (Nn/16, 2): y=0 fs->fes, y=1 ft->fet. 128 thr.
__global__ void embed_kernel(const float* __restrict__ fs, const float* __restrict__ ft,
                             const float* __restrict__ W, const float* __restrict__ b) {
    const float* X = blockIdx.y ? ft : fs;
    float* OUT = blockIdx.y ? g_fet : g_fes;
    int d = threadIdx.x;
    int R0 = blockIdx.x * 16;
    __shared__ __align__(16) float srow[16][64];
    __shared__ float sW[64][Dd];
    __shared__ float sred[16][132];
    __shared__ float sscale[16];
    float acc[16];
#pragma unroll
    for (int r = 0; r < 16; r++) acc[r] = 0.f;
    for (int kc = 0; kc < Cc; kc += 64) {
        __syncthreads();
        for (int u = d; u < 256; u += Dd) { int r = u >> 4, kq = u & 15;
            ((float4*)srow[r])[kq] = *(const float4*)&X[(size_t)(R0 + r) * Cc + kc + kq*4]; }
        for (int k = 0; k < 64; k++) sW[k][d] = W[(size_t)(kc + k) * Dd + d];
        __syncthreads();
#pragma unroll 4
        for (int k4 = 0; k4 < 16; k4++) {
            float w0 = sW[k4*4+0][d], w1 = sW[k4*4+1][d], w2 = sW[k4*4+2][d], w3 = sW[k4*4+3][d];
#pragma unroll
            for (int r = 0; r < 16; r++) {
                float4 s4 = ((float4*)srow[r])[k4];
                acc[r] += s4.x*w0; acc[r] += s4.y*w1; acc[r] += s4.z*w2; acc[r] += s4.w*w3;
            }
        }
    }
    float bb = b[d];
#pragma unroll
    for (int r = 0; r < 16; r++) sred[r][d] = acc[r] + bb;
    __syncthreads();
    int lane = d & 31, w = d >> 5;
#pragma unroll
    for (int m = 0; m < 4; m++) {
        int r = w*4 + m;
        float x0 = sred[r][lane], x1 = sred[r][lane+32], x2 = sred[r][lane+64], x3 = sred[r][lane+96];
        float s = x0*x0 + x1*x1 + x2*x2 + x3*x3;
#pragma unroll
        for (int o = 16; o; o >>= 1) s += __shfl_xor_sync(0xffffffffu, s, o);
        if (lane == 0) sscale[r] = rsqrtf(s);
    }
    __syncthreads();
#pragma unroll
    for (int r = 0; r < 16; r++) OUT[(size_t)(R0 + r) * Dd + d] = sred[r][d] * sscale[r];
}

// TAGConv linear + l2norm (+ optional scores on teacher branch). grid (n/16, 2), 128 thr.
__global__ void lin_kernel(const float* __restrict__ X0t, const float* __restrict__ X1t,
                           const float* __restrict__ X2t,
                           const float* __restrict__ X0s, const float* __restrict__ X1s,
                           const float* __restrict__ X2s,
                           int nparts, const float* __restrict__ W, const float* __restrict__ b,
                           float* __restrict__ OUTt, float* __restrict__ OUTs,
                           const float* __restrict__ Wp, const float* __restrict__ bp,
                           int do_score) {
    const float* Xs[3];
    float* OUT;
    if (blockIdx.y) { Xs[0] = X0s; Xs[1] = X1s; Xs[2] = X2s; OUT = OUTs; }
    else            { Xs[0] = X0t; Xs[1] = X1t; Xs[2] = X2t; OUT = OUTt; }
    int d = threadIdx.x;
    int R0 = blockIdx.x * 16;
    __shared__ __align__(16) float srow[16][64];
    __shared__ float sW[64][Dd];
    __shared__ float sred[16][132];
    __shared__ float sscale[16];
    float acc[16];
#pragma unroll
    for (int r = 0; r < 16; r++) acc[r] = 0.f;
    int K = nparts * Dd;
    for (int kc = 0; kc < K; kc += 64) {
        const float* Xp = Xs[kc >> 7];
        int off = kc & 127;
        __syncthreads();
        for (int u = d; u < 256; u += Dd) { int r = u >> 4, kq = u & 15;
            ((float4*)srow[r])[kq] = *(const float4*)&Xp[(size_t)(R0 + r) * Dd + off + kq*4]; }
        for (int k = 0; k < 64; k++) sW[k][d] = W[(size_t)(kc + k) * Dd + d];
        __syncthreads();
#pragma unroll 4
        for (int k4 = 0; k4 < 16; k4++) {
            float w0 = sW[k4*4+0][d], w1 = sW[k4*4+1][d], w2 = sW[k4*4+2][d], w3 = sW[k4*4+3][d];
#pragma unroll
            for (int r = 0; r < 16; r++) {
                float4 s4 = ((float4*)srow[r])[k4];
                acc[r] += s4.x*w0; acc[r] += s4.y*w1; acc[r] += s4.z*w2; acc[r] += s4.w*w3;
            }
        }
    }
    float bb = b[d];
#pragma unroll
    for (int r = 0; r < 16; r++) sred[r][d] = acc[r] + bb;
    __syncthreads();
    int lane = d & 31, w = d >> 5;
    bool sc = do_score && (blockIdx.y == 0);
    float wp0 = 0.f, wp1 = 0.f, wp2 = 0.f, wp3 = 0.f;
    if (sc) { wp0 = Wp[lane]; wp1 = Wp[lane+32]; wp2 = Wp[lane+64]; wp3 = Wp[lane+96]; }
#pragma unroll
    for (int m = 0; m < 4; m++) {
        int r = w*4 + m;
        float x0 = sred[r][lane], x1 = sred[r][lane+32], x2 = sred[r][lane+64], x3 = sred[r][lane+96];
        float s = x0*x0 + x1*x1 + x2*x2 + x3*x3;
        float sp = x0*wp0 + x1*wp1 + x2*wp2 + x3*wp3;
#pragma unroll
        for (int o = 16; o; o >>= 1) { s += __shfl_xor_sync(0xffffffffu, s, o);
                                       sp += __shfl_xor_sync(0xffffffffu, sp, o); }
        if (lane == 0) {
            float scale = rsqrtf(s);
            sscale[r] = scale;
            if (sc) g_scores[R0 + r] = 1.f / (1.f + expf(-(sp * scale + bp[0])));
        }
    }
    __syncthreads();
#pragma unroll
    for (int r = 0; r < 16; r++) OUT[(size_t)(R0 + r) * Dd + d] = sred[r][d] * sscale[r];
}

// A = (fet @ fet^T > 0) with forced diag -> bitmask. Symmetric: lower-triangle tiles, mirrored.
__global__ void gramA_kernel() {
    int l = blockIdx.x;
    int by = (int)((sqrtf(8.f * l + 1.f) - 1.f) * 0.5f);
    while ((by + 1) * (by + 2) / 2 <= l) by++;
    while (by * (by + 1) / 2 > l) by--;
    int bx = l - by * (by + 1) / 2;
    int I0 = by * 64, J0 = bx * 64;
    __shared__ __align__(16) float sx[64*68];
    __shared__ __align__(16) float sy[64*68];
    __shared__ unsigned sbits[64][2], tbits[64][2];
    int t = threadIdx.x, tx = t & 15, ty = t >> 4;
    float acc[4][4];
#pragma unroll
    for (int a = 0; a < 4; a++)
#pragma unroll
        for (int c = 0; c < 4; c++) acc[a][c] = 0.f;
    for (int kc = 0; kc < Dd; kc += 64) {
        __syncthreads();
        for (int u = t; u < 4096; u += 256) { int k = u & 63, r = u >> 6;
            sx[k*68 + r] = g_fet[(size_t)(I0 + r) * Dd + kc + k];
            sy[k*68 + r] = g_fet[(size_t)(J0 + r) * Dd + kc + k]; }
        __syncthreads();
#pragma unroll 8
        for (int k = 0; k < 64; k++) {
            float4 a4 = *(const float4*)&sx[k*68 + ty*4];
            float4 b4 = *(const float4*)&sy[k*68 + tx*4];
            acc[0][0] += a4.x*b4.x; acc[0][1] += a4.x*b4.y; acc[0][2] += a4.x*b4.z; acc[0][3] += a4.x*b4.w;
            acc[1][0] += a4.y*b4.x; acc[1][1] += a4.y*b4.y; acc[1][2] += a4.y*b4.z; acc[1][3] += a4.y*b4.w;
            acc[2][0] += a4.z*b4.x; acc[2][1] += a4.z*b4.y; acc[2][2] += a4.z*b4.z; acc[2][3] += a4.z*b4.w;
            acc[3][0] += a4.w*b4.x; acc[3][1] += a4.w*b4.y; acc[3][2] += a4.w*b4.z; acc[3][3] += a4.w*b4.w;
        }
    }
    __syncthreads();
    if (t < 128) { ((unsigned*)sbits)[t] = 0; ((unsigned*)tbits)[t] = 0; }
    __syncthreads();
    int wj = (tx * 4) >> 5, shj = (tx * 4) & 31;
    int wi = (ty * 4) >> 5, shi = (ty * 4) & 31;
#pragma unroll
    for (int rr = 0; rr < 4; rr++) {
        int i = I0 + ty*4 + rr;
        unsigned nib = 0;
#pragma unroll
        for (int cc = 0; cc < 4; cc++) {
            int j = J0 + tx*4 + cc;
            if (acc[rr][cc] > 0.f || i == j) nib |= 1u << cc;
        }
        if (nib) atomicOr(&sbits[ty*4 + rr][wj], nib << shj);
    }
#pragma unroll
    for (int cc = 0; cc < 4; cc++) {
        int j = J0 + tx*4 + cc;
        unsigned nib = 0;
#pragma unroll
        for (int rr = 0; rr < 4; rr++) {
            int i = I0 + ty*4 + rr;
            if (acc[rr][cc] > 0.f || i == j) nib |= 1u << rr;
        }
        if (nib) atomicOr(&tbits[tx*4 + cc][wi], nib << shi);
    }
    __syncthreads();
    if (t < 128) {
        int il = t >> 1, ww = t & 1;
        g_Abits[(size_t)(I0 + il) * 64 + (J0 >> 5) + ww] = sbits[il][ww];
        g_Abits[(size_t)(J0 + il) * 64 + (I0 >> 5) + ww] = tbits[il][ww];
    }
}

__global__ void dinv_kernel() {
    int i = blockIdx.x * blockDim.x + threadIdx.x;
    if (i >= Nn) return;
    const uint4* p = (const uint4*)&g_Abits[(size_t)i * 64];
    int dg = 0;
#pragma unroll
    for (int w = 0; w < 16; w++) { uint4 v = p[w];
        dg += __popc(v.x) + __popc(v.y) + __popc(v.z) + __popc(v.w); }
    g_dinv[i] = rsqrtf((float)dg);
}

// partial[i,d] = sum_{j in chunk: bit(i,j)} dinv_j * H[j,d]  (no dinv_i scale)
// grid (n/64, 2, 2*ns): z -> ts = z/ns, split = z%ns. 256 thr.
__global__ void __launch_bounds__(256) prop_partial(
        const float* __restrict__ Ht, const float* __restrict__ Hs,
        const unsigned* __restrict__ bits, const float* __restrict__ dinv,
        int n, int nwords, int ns) {
    int z = blockIdx.z;
    int ts = z / ns, split = z - ts * ns;
    const float* H = ts ? Hs : Ht;
    int t = threadIdx.x, tx = t & 15, ty = t >> 4;
    int I0 = blockIdx.x * 64, D0 = blockIdx.y * 64;
    int r0 = I0 + ty * 4;
    int chunk = n / ns;
    int jbeg = split * chunk;
    __shared__ __align__(16) float sh[32*72];
    float acc[4][4];
#pragma unroll
    for (int a = 0; a < 4; a++)
#pragma unroll
        for (int c = 0; c < 4; c++) acc[a][c] = 0.f;
    for (int j0 = jbeg; j0 < jbeg + chunk; j0 += 32) {
        __syncthreads();
        for (int u = t; u < 512; u += 256) {
            int j = u >> 4, dq = u & 15;
            float4 v = *(const float4*)&H[(size_t)(j0 + j) * Dd + D0 + dq*4];
            float di = dinv[j0 + j];
            v.x *= di; v.y *= di; v.z *= di; v.w *= di;
            *(float4*)&sh[j*72 + dq*4] = v;
        }
        __syncthreads();
        int wi = j0 >> 5;
        unsigned w0 = bits[(size_t)(r0 + 0) * nwords + wi];
        unsigned w1 = bits[(size_t)(r0 + 1) * nwords + wi];
        unsigned w2 = bits[(size_t)(r0 + 2) * nwords + wi];
        unsigned w3 = bits[(size_t)(r0 + 3) * nwords + wi];
#pragma unroll
        for (int k = 0; k < 32; k++) {
            float4 b4 = *(const float4*)&sh[k*72 + tx*4];
            unsigned m = 1u << k;
            if (w0 & m) { acc[0][0]+=b4.x; acc[0][1]+=b4.y; acc[0][2]+=b4.z; acc[0][3]+=b4.w; }
            if (w1 & m) { acc[1][0]+=b4.x; acc[1][1]+=b4.y; acc[1][2]+=b4.z; acc[1][3]+=b4.w; }
            if (w2 & m) { acc[2][0]+=b4.x; acc[2][1]+=b4.y; acc[2][2]+=b4.z; acc[2][3]+=b4.w; }
            if (w3 & m) { acc[3][0]+=b4.x; acc[3][1]+=b4.y; acc[3][2]+=b4.z; acc[3][3]+=b4.w; }
        }
    }
    float* pp = g_pp + (size_t)(ts * ns + split) * n * Dd;
#pragma unroll
    for (int rr = 0; rr < 4; rr++)
        *(float4*)&pp[(size_t)(r0 + rr) * Dd + D0 + tx*4] =
            make_float4(acc[rr][0], acc[rr][1], acc[rr][2], acc[rr][3]);
}

// O[i,d] = dinv_i * sum_k partial_k[i,d]. grid (n*32/256, 2), 256 thr (float4 each).
__global__ void prop_combine(float* __restrict__ Ot, float* __restrict__ Os,
                             const float* __restrict__ dinv, int n, int ns) {
    int ts = blockIdx.y;
    float* O = ts ? Os : Ot;
    int idx = blockIdx.x * blockDim.x + threadIdx.x;   // float4 index
    if (idx >= n * 32) return;
    int row = idx >> 5;
    float4 s = make_float4(0.f, 0.f, 0.f, 0.f);
    for (int k = 0; k < ns; k++) {
        float4 v = *(const float4*)&g_pp[(size_t)(ts * ns + k) * n * Dd + (size_t)idx * 4];
        s.x += v.x; s.y += v.y; s.z += v.z; s.w += v.w;
    }
    float di = dinv[row];
    s.x *= di; s.y *= di; s.z *= di; s.w *= di;
    *(float4*)&O[(size_t)idx * 4] = s;
}

// G = X @ Y^T; per-tile partial row/col sums of exp((G-1)/T); diag tiles emit pos.
__global__ void gramnce_kernel(const float* __restrict__ X, const float* __restrict__ Y,
                               float* __restrict__ rowp, float* __restrict__ colp,
                               float* __restrict__ pos, int n) {
    __shared__ __align__(16) float sx[64*68];
    __shared__ __align__(16) float sy[64*68];
    __shared__ float cbuf[16][64];
    int t = threadIdx.x, tx = t & 15, ty = t >> 4;
    int I0 = blockIdx.y * 64, J0 = blockIdx.x * 64;
    float acc[4][4];
#pragma unroll
    for (int a = 0; a < 4; a++)
#pragma unroll
        for (int c = 0; c < 4; c++) acc[a][c] = 0.f;
    for (int kc = 0; kc < Dd; kc += 64) {
        __syncthreads();
        for (int u = t; u < 4096; u += 256) { int k = u & 63, r = u >> 6;
            sx[k*68 + r] = X[(size_t)(I0 + r) * Dd + kc + k];
            sy[k*68 + r] = Y[(size_t)(J0 + r) * Dd + kc + k]; }
        __syncthreads();
#pragma unroll 8
        for (int k = 0; k < 64; k++) {
            float4 a4 = *(const float4*)&sx[k*68 + ty*4];
            float4 b4 = *(const float4*)&sy[k*68 + tx*4];
            acc[0][0] += a4.x*b4.x; acc[0][1] += a4.x*b4.y; acc[0][2] += a4.x*b4.z; acc[0][3] += a4.x*b4.w;
            acc[1][0] += a4.y*b4.x; acc[1][1] += a4.y*b4.y; acc[1][2] += a4.y*b4.z; acc[1][3] += a4.y*b4.w;
            acc[2][0] += a4.z*b4.x; acc[2][1] += a4.z*b4.y; acc[2][2] += a4.z*b4.z; acc[2][3] += a4.z*b4.w;
            acc[3][0] += a4.w*b4.x; acc[3][1] += a4.w*b4.y; acc[3][2] += a4.w*b4.z; acc[3][3] += a4.w*b4.w;
        }
    }
    if (I0 == J0) {
#pragma unroll
        for (int rr = 0; rr < 4; rr++) {
            int dd = ty*4 + rr - tx*4;
            if (dd >= 0 && dd < 4) pos[I0 + ty*4 + rr] = acc[rr][dd];
        }
    }
    float e[4][4];
#pragma unroll
    for (int rr = 0; rr < 4; rr++) {
        float rl = 0.f;
#pragma unroll
        for (int cc = 0; cc < 4; cc++) {
            e[rr][cc] = expf((acc[rr][cc] - 1.f) * TINV);
            rl += e[rr][cc];
        }
#pragma unroll
        for (int o = 8; o; o >>= 1) rl += __shfl_xor_sync(0xffffffffu, rl, o);
        if (tx == 0) rowp[(size_t)blockIdx.x * n + I0 + ty*4 + rr] = rl;
    }
#pragma unroll
    for (int cc = 0; cc < 4; cc++)
        cbuf[ty][tx*4 + cc] = e[0][cc] + e[1][cc] + e[2][cc] + e[3][cc];
    __syncthreads();
    if (t < 64) {
        float s = 0.f;
#pragma unroll
        for (int y = 0; y < 16; y++) s += cbuf[y][t];
        colp[(size_t)blockIdx.y * n + J0 + t] = s;
    }
}

// rank[i] = #{j: s_j > s_i} + #{j<i: s_j == s_i}; permutation -> direct slot write.
__global__ void rank_kernel() {
    int i = blockIdx.x, t = threadIdx.x;
    float si = g_scores[i];
    int c = 0;
    for (int j = t; j < Nn; j += 256) {
        float sj = g_scores[j];
        c += (sj > si) || (sj == si && j < i);
    }
    __shared__ int rb[256];
    rb[t] = c; __syncthreads();
    for (int s = 128; s; s >>= 1) { if (t < s) rb[t] += rb[t + s]; __syncthreads(); }
    if (t == 0) {
        int r = rb[0];
        if (r < Kp) { g_selidx[r] = i; g_selval[r] = si; }
    }
}

// new_h = f_g[idx] * val. grid Kp, 128 thr.
__global__ void gather_kernel() {
    int p = blockIdx.x, d = threadIdx.x;
    int i = g_selidx[p];
    float v = g_selval[p];
    g_nht[(size_t)p * Dd + d] = g_fgt[(size_t)i * Dd + d] * v;
    g_nhs[(size_t)p * Dd + d] = g_fgs[(size_t)i * Dd + d] * v;
}

// sub[p][q] = rows idx_p, idx_q of A intersect. grid (16,16), 256 thr. uint4 loads.
__global__ void subbits_kernel() {
    __shared__ __align__(16) unsigned pr[64*68];
    __shared__ __align__(16) unsigned qr[64*68];
    __shared__ unsigned pb[64][2];
    int t = threadIdx.x;
    int P0 = blockIdx.y * 64, Q0 = blockIdx.x * 64;
    for (int u = t; u < 1024; u += 256) {
        int r = u >> 4, w4 = u & 15;
        *(uint4*)&pr[r*68 + w4*4] = *(const uint4*)&g_Abits[(size_t)g_selidx[P0 + r] * 64 + w4*4];
        *(uint4*)&qr[r*68 + w4*4] = *(const uint4*)&g_Abits[(size_t)g_selidx[Q0 + r] * 64 + w4*4];
    }
    if (t < 128) ((unsigned*)pb)[t] = 0;
    __syncthreads();
    int p = t >> 2, qb = t & 3;
    unsigned anyv[16];
#pragma unroll
    for (int qq = 0; qq < 16; qq++) anyv[qq] = 0;
    for (int w4 = 0; w4 < 16; w4++) {
        uint4 a = *(const uint4*)&pr[p*68 + w4*4];
#pragma unroll
        for (int qq = 0; qq < 16; qq++) {
            uint4 bv = *(const uint4*)&qr[(qb*16 + qq)*68 + w4*4];
            anyv[qq] |= (a.x & bv.x) | (a.y & bv.y) | (a.z & bv.z) | (a.w & bv.w);
        }
    }
    unsigned res = 0;
#pragma unroll
    for (int qq = 0; qq < 16; qq++) res |= (anyv[qq] ? 1u : 0u) << qq;
    atomicOr(&pb[p][qb >> 1], res << ((qb & 1) * 16));
    __syncthreads();
    if (t < 128) g_Pbits[(size_t)(P0 + (t >> 1)) * 32 + (Q0 >> 5) + (t & 1)] = pb[t >> 1][t & 1];
}

__global__ void dinvp_kernel() {
    int p = blockIdx.x * blockDim.x + threadIdx.x;
    if (p >= Kp) return;
    const uint4* q = (const uint4*)&g_Pbits[(size_t)p * 32];
    int dg = 0;
#pragma unroll
    for (int w = 0; w < 8; w++) { uint4 v = q[w];
        dg += __popc(v.x) + __popc(v.y) + __popc(v.z) + __popc(v.w); }
    g_dinvp[p] = rsqrtf((float)dg);
}

// terms + final reduce, single block 1024 thr.
__global__ void final_kernel(float* __restrict__ out) {
    int t = threadIdx.x;
    float s1 = 0.f, s2 = 0.f;
    for (int i = t; i < Nn; i += 1024) {
        float rs = 0.f, cs = 0.f;
        for (int k = 0; k < 32; k++) { rs += g_rowp1[(size_t)k * Nn + i]; cs += g_colp1[(size_t)k * Nn + i]; }
        s1 += logf(rs) + logf(cs) + 2.f * (1.f - g_pos1[i]) * TINV;
    }
    for (int i = t; i < Kp; i += 1024) {
        float rs = 0.f, cs = 0.f;
        for (int k = 0; k < 16; k++) { rs += g_rowp2[(size_t)k * Kp + i]; cs += g_colp2[(size_t)k * Kp + i]; }
        s2 += logf(rs) + logf(cs) + 2.f * (1.f - g_pos2[i]) * TINV;
    }
    __shared__ float r1[1024], r2[1024];
    r1[t] = s1; r2[t] = s2; __syncthreads();
    for (int s = 512; s; s >>= 1) { if (t < s) { r1[t] += r1[t + s]; r2[t] += r2[t + s]; } __syncthreads(); }
    if (t == 0) out[0] = r1[0] / (float)Nn + r2[0] / (float)Kp;
}

// ----------------- launch -----------------

template <typename T> static T* sym(const T& s) {
    void* p = nullptr;
    cudaGetSymbolAddress(&p, s);
    return (T*)p;
}

extern "C" void kernel_launch(void* const* d_in, const int* in_sizes, int n_in,
                              void* d_out, int out_size) {
    const float* fs  = (const float*)d_in[0];
    const float* ft  = (const float*)d_in[1];
    const float* We  = (const float*)d_in[2];
    const float* be  = (const float*)d_in[3];
    const float* Wg  = (const float*)d_in[4];
    const float* bg  = (const float*)d_in[5];
    const float* Wp  = (const float*)d_in[6];
    const float* bp  = (const float*)d_in[7];
    const float* Wgp = (const float*)d_in[8];
    const float* bgp = (const float*)d_in[9];
    float* out = (float*)d_out;

    float* fes = (float*)sym(g_fes);   float* fet = (float*)sym(g_fet);
    float* h1t = (float*)sym(g_h1t);   float* h1s = (float*)sym(g_h1s);
    float* h2t = (float*)sym(g_h2t);   float* h2s = (float*)sym(g_h2s);
    float* fgt = (float*)sym(g_fgt);   float* fgs = (float*)sym(g_fgs);
    float* nht = (float*)sym(g_nht);   float* nhs = (float*)sym(g_nhs);
    float* ph1t = (float*)sym(g_ph1t); float* ph1s = (float*)sym(g_ph1s);
    float* fpt = (float*)sym(g_fpt);   float* fps = (float*)sym(g_fps);
    float* dinv = (float*)sym(g_dinv); float* dinvp = (float*)sym(g_dinvp);
    unsigned* Ab = (unsigned*)sym(g_Abits);
    unsigned* Pb = (unsigned*)sym(g_Pbits);
    float* rowp1 = (float*)sym(g_rowp1); float* colp1 = (float*)sym(g_colp1);
    float* rowp2 = (float*)sym(g_rowp2); float* colp2 = (float*)sym(g_colp2);
    float* pos1 = (float*)sym(g_pos1);   float* pos2 = (float*)sym(g_pos2);

    embed_kernel<<<dim3(Nn/16, 2), 128>>>(fs, ft, We, be);
    gramA_kernel<<<528, 256>>>();
    dinv_kernel<<<8, 256>>>();
    prop_partial<<<dim3(32, 2, 16), 256>>>(fet, fes, Ab, dinv, Nn, 64, 8);
    prop_combine<<<dim3(256, 2), 256>>>(h1t, h1s, dinv, Nn, 8);
    prop_partial<<<dim3(32, 2, 16), 256>>>(h1t, h1s, Ab, dinv, Nn, 64, 8);
    prop_combine<<<dim3(256, 2), 256>>>(h2t, h2s, dinv, Nn, 8);
    lin_kernel<<<dim3(Nn/16, 2), 128>>>(fet, h1t, h2t, fes, h1s, h2s, 3, Wg, bg, fgt, fgs, Wp, bp, 1);
    gramnce_kernel<<<dim3(32, 32), 256>>>(fgt, fgs, rowp1, colp1, pos1, Nn);
    rank_kernel<<<Nn, 256>>>();
    gather_kernel<<<Kp, 128>>>();
    subbits_kernel<<<dim3(16, 16), 256>>>();
    dinvp_kernel<<<4, 256>>>();
    prop_partial<<<dim3(16, 2, 8), 256>>>(nht, nhs, Pb, dinvp, Kp, 32, 4);
    prop_combine<<<dim3(128, 2), 256>>>(ph1t, ph1s, dinvp, Kp, 4);
    lin_kernel<<<dim3(Kp/16, 2), 128>>>(nht, ph1t, nullptr, nhs, ph1s, nullptr, 2, Wgp, bgp, fpt, fps, nullptr, nullptr, 0);
    gramnce_kernel<<<dim3(16, 16), 256>>>(fpt, fps, rowp2, colp2, pos2, Kp);
    final_kernel<<<1, 1024>>>(out);
}